// round 7
// baseline (speedup 1.0000x reference)
#include <cuda_runtime.h>
#include <stdint.h>

#define NTOK  8192      // BATCH * SEQ
#define D     256       // EMBED_DIM
#define NR    100       // NUM_RULES
#define COLT  64        // output-column tile per block
#define TT    32        // token tile per iteration
#define KC    4         // token-chunk grid dimension (load balancing)
#define BPAD  260       // padded base row stride (floats); breaks bank conflicts

// ---------------- scratch (device globals; no allocation allowed) ----------------
__device__ int g_count[NR];
__device__ int g_offset[NR + 1];
__device__ int g_cursor[NR];
__device__ int g_bucket[NTOK];   // token flat-indices grouped by rule
__device__ int g_ruleof[NTOK];   // cached rule per token

// ---------------- phase 1: histogram ----------------
__global__ void k_zero() {
    int i = threadIdx.x;
    if (i < NR) g_count[i] = 0;
}

__global__ void k_count(const int* __restrict__ token_ids,
                        const int* __restrict__ token_rules) {
    int i = blockIdx.x * blockDim.x + threadIdx.x;
    if (i < NTOK) {
        int r = token_rules[token_ids[i]];
        g_ruleof[i] = r;
        atomicAdd(&g_count[r], 1);
    }
}

// ---------------- phase 2: exclusive scan (100 elems, serial) ----------------
__global__ void k_scan() {
    if (threadIdx.x == 0) {
        int acc = 0;
        for (int r = 0; r < NR; r++) {
            g_offset[r] = acc;
            g_cursor[r] = acc;
            acc += g_count[r];
        }
        g_offset[NR] = acc;
    }
}

// ---------------- phase 3: scatter into buckets ----------------
__global__ void k_scatter() {
    int i = blockIdx.x * blockDim.x + threadIdx.x;
    if (i < NTOK) {
        int r = g_ruleof[i];
        int p = atomicAdd(&g_cursor[r], 1);
        g_bucket[p] = i;
    }
}

// ---------------- phase 4: per-rule batched GEMM ----------------
// grid: (D/COLT, NR, KC). block: 128 threads = 8 rowgroups x 16 colgroups.
// Block (x,y,z) handles rule y, cols [x*64, x*64+64), token tiles z, z+KC, ...
// Each thread: 4 tokens x 4 cols, packed fma.rn.f32x2 (full fp32 precision).
// smem: sM [256][64] f32 (64KB) + sB [32][BPAD] f32 (~33.3KB) -> occupancy 2.
__global__ __launch_bounds__(128, 2)
void k_gemm(const int* __restrict__ token_ids,
            const float* __restrict__ base,
            const float* __restrict__ rules,
            float* __restrict__ out) {
    const int r   = blockIdx.y;
    const int c0  = blockIdx.x * COLT;
    const int off = g_offset[r];
    const int n   = g_offset[r + 1] - off;
    const int tstart = (int)blockIdx.z * TT;
    if (tstart >= n) return;   // nothing for this chunk lane: exit before any smem work

    extern __shared__ float sm[];
    float* sM = sm;                 // [256][64]
    float* sB = sm + D * COLT;      // [32][BPAD]
    const int tid = threadIdx.x;

    // Load M[r][:, c0:c0+64] into smem. Coalesced float4 loads. 32 iters/thread.
    const float* Mg = rules + (size_t)r * D * D + c0;
    #pragma unroll
    for (int i = tid; i < D * (COLT / 4); i += 128) {
        int d = i >> 4, v = i & 15;
        *(float4*)(sM + d * COLT + v * 4) = *(const float4*)(Mg + (size_t)d * D + v * 4);
    }
    __syncthreads();

    const int row = tid >> 4;         // 0..7
    const int cg  = (tid & 15) * 4;   // 0,4,...,60
    const int t00 = row * 4;          // first of 4 tokens for this thread

    for (int t0 = tstart; t0 < n; t0 += KC * TT) {
        const int nt = min(TT, n - t0);
        __syncthreads();  // previous tile's readers done before overwriting sB

        // Gather up to 32 token embeddings into padded smem rows. 16 iters/thread.
        for (int i = tid; i < TT * (D / 4); i += 128) {
            int tk = i >> 6, v = i & 63;
            float4 val = make_float4(0.f, 0.f, 0.f, 0.f);
            if (tk < nt) {
                int flat = g_bucket[off + t0 + tk];
                int tok  = token_ids[flat];
                val = *(const float4*)(base + (size_t)tok * D + v * 4);
            }
            *(float4*)(sB + tk * BPAD + v * 4) = val;
        }
        __syncthreads();

        // acc[j] = {col pair 0 (m.x), col pair 1 (m.y)} for token t00+j
        unsigned long long acc[4][2];
        #pragma unroll
        for (int j = 0; j < 4; ++j) { acc[j][0] = 0ULL; acc[j][1] = 0ULL; }

        const float* b0 = sB + (t00 + 0) * BPAD;
        const float* b1 = sB + (t00 + 1) * BPAD;
        const float* b2 = sB + (t00 + 2) * BPAD;
        const float* b3 = sB + (t00 + 3) * BPAD;

        #pragma unroll 2
        for (int d = 0; d < D; d += 4) {
            float4 v0 = *(const float4*)(b0 + d);
            float4 v1 = *(const float4*)(b1 + d);
            float4 v2 = *(const float4*)(b2 + d);
            float4 v3 = *(const float4*)(b3 + d);
            #pragma unroll
            for (int u = 0; u < 4; ++u) {
                ulonglong2 m = *(const ulonglong2*)(sM + (d + u) * COLT + cg);
                float f0 = (u == 0) ? v0.x : (u == 1) ? v0.y : (u == 2) ? v0.z : v0.w;
                float f1 = (u == 0) ? v1.x : (u == 1) ? v1.y : (u == 2) ? v1.z : v1.w;
                float f2 = (u == 0) ? v2.x : (u == 1) ? v2.y : (u == 2) ? v2.z : v2.w;
                float f3 = (u == 0) ? v3.x : (u == 1) ? v3.y : (u == 2) ? v3.z : v3.w;
                unsigned int s0 = __float_as_uint(f0), s1 = __float_as_uint(f1);
                unsigned int s2 = __float_as_uint(f2), s3 = __float_as_uint(f3);
                unsigned long long p0, p1, p2, p3;
                asm("mov.b64 %0, {%1,%1};" : "=l"(p0) : "r"(s0));
                asm("mov.b64 %0, {%1,%1};" : "=l"(p1) : "r"(s1));
                asm("mov.b64 %0, {%1,%1};" : "=l"(p2) : "r"(s2));
                asm("mov.b64 %0, {%1,%1};" : "=l"(p3) : "r"(s3));
                asm("fma.rn.f32x2 %0, %1, %2, %0;" : "+l"(acc[0][0]) : "l"(m.x), "l"(p0));
                asm("fma.rn.f32x2 %0, %1, %2, %0;" : "+l"(acc[0][1]) : "l"(m.y), "l"(p0));
                asm("fma.rn.f32x2 %0, %1, %2, %0;" : "+l"(acc[1][0]) : "l"(m.x), "l"(p1));
                asm("fma.rn.f32x2 %0, %1, %2, %0;" : "+l"(acc[1][1]) : "l"(m.y), "l"(p1));
                asm("fma.rn.f32x2 %0, %1, %2, %0;" : "+l"(acc[2][0]) : "l"(m.x), "l"(p2));
                asm("fma.rn.f32x2 %0, %1, %2, %0;" : "+l"(acc[2][1]) : "l"(m.y), "l"(p2));
                asm("fma.rn.f32x2 %0, %1, %2, %0;" : "+l"(acc[3][0]) : "l"(m.x), "l"(p3));
                asm("fma.rn.f32x2 %0, %1, %2, %0;" : "+l"(acc[3][1]) : "l"(m.y), "l"(p3));
            }
        }

        #pragma unroll
        for (int j = 0; j < 4; ++j) {
            int t = t00 + j;
            if (t < nt) {
                int flat = g_bucket[off + t0 + t];
                unsigned int lo, hi;
                float4 v;
                asm("mov.b64 {%0,%1}, %2;" : "=r"(lo), "=r"(hi) : "l"(acc[j][0]));
                v.x = __uint_as_float(lo); v.y = __uint_as_float(hi);
                asm("mov.b64 {%0,%1}, %2;" : "=r"(lo), "=r"(hi) : "l"(acc[j][1]));
                v.z = __uint_as_float(lo); v.w = __uint_as_float(hi);
                *(float4*)(out + (size_t)flat * D + c0 + cg) = v;
            }
        }
    }
}

// ---------------- launch ----------------
extern "C" void kernel_launch(void* const* d_in, const int* in_sizes, int n_in,
                              void* d_out, int out_size) {
    const int*   token_ids   = (const int*)d_in[0];    // [4,2048] int32
    const float* base        = (const float*)d_in[1];  // [32000,256] f32
    const float* rules       = (const float*)d_in[2];  // [100,256,256] f32
    const int*   token_rules = (const int*)d_in[3];    // [32000] int32
    float*       out         = (float*)d_out;          // [4,2048,256] f32

    const int SMEM = (D * COLT + TT * BPAD) * (int)sizeof(float);  // 98816 B
    cudaFuncSetAttribute(k_gemm, cudaFuncAttributeMaxDynamicSharedMemorySize, SMEM);

    k_zero<<<1, 128>>>();
    k_count<<<(NTOK + 255) / 256, 256>>>(token_ids, token_rules);
    k_scan<<<1, 32>>>();
    k_scatter<<<(NTOK + 255) / 256, 256>>>();
    k_gemm<<<dim3(D / COLT, NR, KC), 128, SMEM>>>(token_ids, base, rules, out);
}